// round 4
// baseline (speedup 1.0000x reference)
#include <cuda_runtime.h>
#include <stdint.h>

#define BATCH 16
#define H 1024
#define W 1024
#define HW (H*W)            // 1<<20
#define NPIX (BATCH*HW)

// ---------------- scratch (static device globals; no allocs) ----------------
// Label encoding: fg pixel -> nonnegative global index of an ancestor (tile root,
// then final root). bg pixel -> (g | 0x80000000), negative, never merged.
__device__ int d_labels[NPIX];
__device__ int d_counts[NPIX];
__device__ unsigned long long d_winner[BATCH];

// ---------------- lock-free union-find (min-index roots) --------------------
// Unions attach larger index under smaller, so every component's final root is
// its MINIMUM linear index == the reference's min-propagation fixed point.
__device__ __forceinline__ int findRootG(int x) {
    int p = d_labels[x];
    while (p != x) { x = p; p = d_labels[x]; }
    return x;
}
__device__ __forceinline__ void uniteG(int a, int b) {
    a = findRootG(a);
    b = findRootG(b);
    while (a != b) {
        if (a < b) { int t = a; a = b; b = t; }
        int old = atomicMin(&d_labels[a], b);
        if (old == a) a = b;
        else a = old;
    }
}
__device__ __forceinline__ int findRootS(int* L, int x) {
    int p = L[x];
    while (p != x) { x = p; p = L[x]; }
    return x;
}
__device__ __forceinline__ void uniteS(int* L, int a, int b) {
    a = findRootS(L, a);
    b = findRootS(L, b);
    while (a != b) {
        if (a < b) { int t = a; a = b; b = t; }
        int old = atomicMin(&L[a], b);
        if (old == a) a = b;
        else a = old;
    }
}

// ---------------- kernel 1: fg + tile-local CC in shared memory -------------
__global__ __launch_bounds__(1024) void k_init_local(const float* __restrict__ x) {
    __shared__ int sl[1024];
    __shared__ unsigned char sf[1024];

    const int tx = threadIdx.x, ty = threadIdx.y;
    const int t = ty * 32 + tx;
    const int b = blockIdx.z;
    const int row = blockIdx.y * 32 + ty;
    const int col = blockIdx.x * 32 + tx;
    const int p = row * W + col;
    const int g = b * HW + p;

    const float* xb = x + (size_t)b * 2 * HW;
    const float v0 = xb[p];
    const float v1 = xb[HW + p];
    const int fg = (v1 > v0) ? 1 : 0;     // argmax over 2 classes, tie -> class 0

    sl[t] = t;
    sf[t] = (unsigned char)fg;
    __syncthreads();

    if (fg) {
        if (tx > 0 && sf[t - 1])            uniteS(sl, t, t - 1);
        if (ty > 0) {
            if (sf[t - 32])                 uniteS(sl, t, t - 32);
            if (tx > 0  && sf[t - 33])      uniteS(sl, t, t - 33);
            if (tx < 31 && sf[t - 31])      uniteS(sl, t, t - 31);
        }
    }
    __syncthreads();

    int lab;
    if (fg) {
        int r = findRootS(sl, t);
        int rrow = blockIdx.y * 32 + (r >> 5);
        int rcol = blockIdx.x * 32 + (r & 31);
        lab = b * HW + rrow * W + rcol;                 // nonnegative
    } else {
        lab = g | 0x80000000;                           // negative marker
    }
    d_labels[g] = lab;
    d_counts[g] = 0;

    if (blockIdx.x == 0 && blockIdx.y == 0 && blockIdx.z == 0 && t < BATCH)
        d_winner[t] = 0ULL;
}

// ---------------- kernel 2: merge across tile borders -----------------------
__global__ void k_border() {
    const int perB = 2 * 31 * 1024;
    int idx = blockIdx.x * blockDim.x + threadIdx.x;
    if (idx >= BATCH * perB) return;
    const int b = idx / perB;
    int j = idx - b * perB;
    const int base = b * HW;

    if (j < 31 * 1024) {
        // horizontal tile boundary rows 32,64,...,992
        const int r = 32 * (1 + (j >> 10));
        const int c = j & 1023;
        const int p = base + r * W + c;
        const int lp = d_labels[p];
        if (lp < 0) return;
        const int up = p - W;
        int ln;
        ln = d_labels[up];
        if (ln >= 0) uniteG(lp, ln);
        if (c > 0)     { ln = d_labels[up - 1]; if (ln >= 0) uniteG(lp, ln); }
        if (c < W - 1) { ln = d_labels[up + 1]; if (ln >= 0) uniteG(lp, ln); }
    } else {
        // vertical tile boundary cols 32,64,...,992
        j -= 31 * 1024;
        const int c = 32 * (1 + (j >> 10));
        const int r = j & 1023;
        const int p = base + r * W + c;
        const int lp = d_labels[p];
        if (lp < 0) return;
        const int lf = p - 1;
        int ln;
        ln = d_labels[lf];
        if (ln >= 0) uniteG(lp, ln);
        if (r > 0)     { ln = d_labels[lf - W]; if (ln >= 0) uniteG(lp, ln); }
        if (r < H - 1) { ln = d_labels[lf + W]; if (ln >= 0) uniteG(lp, ln); }
    }
}

// ---------------- kernel 3: flatten via shared root cache + count + winner --
// Block = one 32x32 tile (same grid as k_init). All labels in a tile are local
// roots or their parents: provably <= 512 distinct values -> 1024-slot hash.
// Only distinct labels are chased to the global root; pixels do shared lookups.
// Counts are accumulated per (root) with atomicAdd; the running partial sum
// feeds an atomicMax winner key (max final count, min root on ties) -- the
// chronologically-last add for each root emits its exact final count, and all
// partials are <= final, so the global max key equals (max count, min root).
#define HSLOTS 1024
__global__ __launch_bounds__(1024) void k_flatten_count() {
    __shared__ int hkey[HSLOTS];
    __shared__ int hroot[HSLOTS];
    __shared__ int hcnt[HSLOTS];
    __shared__ unsigned long long blockmax;

    const int tx = threadIdx.x, ty = threadIdx.y;
    const int tid = ty * 32 + tx;
    const int b = blockIdx.z;
    const int row = blockIdx.y * 32 + ty;
    const int col = blockIdx.x * 32 + tx;
    const int g = b * HW + row * W + col;

    hkey[tid] = -1;
    hcnt[tid] = 0;
    if (tid == 0) blockmax = 0ULL;
    __syncthreads();

    const int lab = d_labels[g];
    int myslot = -1;
    if (lab >= 0) {
        unsigned h = ((unsigned)lab * 2654435761u) >> 22;   // 10-bit hash
        for (;;) {
            int k = atomicCAS(&hkey[h & (HSLOTS - 1)], -1, lab);
            if (k == -1 || k == lab) { myslot = h & (HSLOTS - 1); break; }
            ++h;
        }
        atomicAdd(&hcnt[myslot], 1);
    }
    __syncthreads();

    // chase distinct labels to global roots (few dozen per tile typically)
    int slotkey = hkey[tid];
    if (slotkey >= 0) {
        int r = findRootG(slotkey);
        hroot[tid] = r;
        d_labels[slotkey] = r;      // benign helpful compression (forest static)
    }
    __syncthreads();

    if (myslot >= 0)
        d_labels[g] = hroot[myslot];

    // per-distinct-root accumulate + winner candidate
    if (slotkey >= 0) {
        const int root = hroot[tid];
        const int cnt = hcnt[tid];
        const int total = atomicAdd(&d_counts[root], cnt) + cnt;
        const unsigned long long key =
            ((unsigned long long)(unsigned)total << 32)
            | (unsigned long long)(0xFFFFFFFFu - (unsigned)root);
        atomicMax(&blockmax, key);
    }
    __syncthreads();

    if (tid == 0 && blockmax != 0ULL) {
        // cheap filter: d_winner only grows, so a stale read only causes an
        // occasional redundant atomicMax, never a miss.
        unsigned long long cur =
            *(volatile unsigned long long*)&d_winner[b];
        if (blockmax > cur) atomicMax(&d_winner[b], blockmax);
    }
}

// ---------------- kernel 4: masked output, vectorized -----------------------
__global__ void k_write(const float* __restrict__ x, float* __restrict__ out) {
    const int i = blockIdx.x * blockDim.x + threadIdx.x;   // over NPIX/4
    const int p4 = i << 2;
    const int b = p4 >> 20;                                // HW = 2^20
    const int p = p4 & (HW - 1);

    const unsigned long long wk = d_winner[b];
    // no foreground -> wk==0 -> wroot=-1, matches nothing (labels are either
    // nonneg roots or 0x80000000|g, never -1 since g < 2^24)
    const int wroot = (int)(0xFFFFFFFFu - (unsigned)(wk & 0xFFFFFFFFu));

    const int4 lab = ((const int4*)d_labels)[i];
    const float* xb = x + (size_t)b * 2 * HW;
    const float4 v0 = *(const float4*)(xb + p);
    const float4 v1 = *(const float4*)(xb + HW + p);

    float4 o0, o1;
    o0.x = (lab.x == wroot) ? v0.x : 0.0f;
    o0.y = (lab.y == wroot) ? v0.y : 0.0f;
    o0.z = (lab.z == wroot) ? v0.z : 0.0f;
    o0.w = (lab.w == wroot) ? v0.w : 0.0f;
    o1.x = (lab.x == wroot) ? v1.x : 0.0f;
    o1.y = (lab.y == wroot) ? v1.y : 0.0f;
    o1.z = (lab.z == wroot) ? v1.z : 0.0f;
    o1.w = (lab.w == wroot) ? v1.w : 0.0f;

    float* ob = out + (size_t)b * 2 * HW;
    *(float4*)(ob + p) = o0;
    *(float4*)(ob + HW + p) = o1;
}

// ---------------- launcher --------------------------------------------------
extern "C" void kernel_launch(void* const* d_in, const int* in_sizes, int n_in,
                              void* d_out, int out_size) {
    const float* x = (const float*)d_in[0];
    float* out = (float*)d_out;

    dim3 blk(32, 32);
    dim3 grd(W / 32, H / 32, BATCH);

    k_init_local<<<grd, blk>>>(x);

    const int nb = BATCH * 2 * 31 * 1024;
    k_border<<<(nb + 255) / 256, 256>>>();

    k_flatten_count<<<grd, blk>>>();

    k_write<<<(NPIX / 4) / 256, 256>>>(x, out);
}

// round 5
// speedup vs baseline: 1.2217x; 1.2217x over previous
#include <cuda_runtime.h>
#include <stdint.h>

#define BATCH 16
#define H 1024
#define W 1024
#define HW (H*W)            // 1<<20
#define NPIX (BATCH*HW)

// ---------------- scratch (static device globals; no allocs) ----------------
// fg pixel label: nonnegative global index of an ancestor (tile-local root).
// bg pixel label: (g | 0x80000000), negative, never merged, never equals winner.
__device__ int d_labels[NPIX];
__device__ int d_counts[NPIX];
__device__ unsigned long long d_winner[BATCH];

// ---------------- shared-memory union-find (min-index roots) ----------------
__device__ __forceinline__ int findRootS(int* L, int x) {
    int p = L[x];
    while (p != x) { x = p; p = L[x]; }
    return x;
}
__device__ __forceinline__ void uniteS(int* L, int a, int b) {
    a = findRootS(L, a);
    b = findRootS(L, b);
    while (a != b) {
        if (a < b) { int t = a; a = b; b = t; }
        int old = atomicMin(&L[a], b);
        if (old == a) a = b;
        else a = old;
    }
}

// ---------------- global union-find with path halving -----------------------
// All writes are atomicMin of an ancestor index: values only decrease and stay
// within the component -> halving is race-safe alongside concurrent unions.
__device__ __forceinline__ int findRootH(int x) {
    int p = d_labels[x];
    while (p != x) {
        int gp = d_labels[p];
        if (gp != p) atomicMin(&d_labels[x], gp);   // halve (no return needed)
        x = p; p = gp;
    }
    return x;
}
__device__ __forceinline__ void uniteG(int a, int b) {
    a = findRootH(a);
    b = findRootH(b);
    while (a != b) {
        if (a < b) { int t = a; a = b; b = t; }
        int old = atomicMin(&d_labels[a], b);
        if (old == a) a = b;
        else a = old;
    }
}

// ---------------- kernel 1: fg + run-based tile-local CC --------------------
// Block = 32x32 tile, warp = row. Within-row runs labeled by their leader via
// ballot bit tricks (no unions). Cross-row unions filtered to ~1 per
// run-adjacency:
//   N fg:            union(t, N)  unless (W fg && NW fg)  [west pixel covers it]
//   N bg && NW fg:   union(t, NW) unless W fg             [W's N-case covers it]
//   N bg && NE fg:   union(t, NE) unless E fg             [E's N-case covers it]
__global__ __launch_bounds__(1024) void k_init_local(const float* __restrict__ x) {
    __shared__ int sl[1024];
    __shared__ unsigned smask[32];

    const int tx = threadIdx.x, ty = threadIdx.y;
    const int t = (ty << 5) | tx;
    const int b = blockIdx.z;
    const int row = (blockIdx.y << 5) + ty;
    const int col = (blockIdx.x << 5) + tx;
    const int p = row * W + col;
    const int g = b * HW + p;

    const float* xb = x + (size_t)b * 2 * HW;
    const int fg = (xb[HW + p] > xb[p]) ? 1 : 0;   // argmax 2 classes, tie->0

    const unsigned rowmask = __ballot_sync(0xFFFFFFFFu, fg);
    if (tx == 0) smask[ty] = rowmask;

    int node = t;
    if (fg) {
        // leader = start of the run containing bit tx
        const unsigned runstarts = rowmask & ~(rowmask << 1);
        const unsigned below = runstarts & ((2u << tx) - 1u);  // tx=31 -> ~0u
        const int leader = 31 - __clz(below);
        node = (ty << 5) | leader;
    }
    sl[t] = node;            // fg non-leader -> leader; leader/bg -> self
    __syncthreads();

    if (fg && ty > 0) {
        const unsigned up = smask[ty - 1];
        const bool Wf  = (tx > 0)  && ((rowmask >> (tx - 1)) & 1u);
        const bool Ef  = (tx < 31) && ((rowmask >> (tx + 1)) & 1u);
        const bool Nf  = (up >> tx) & 1u;
        const bool NWf = (tx > 0)  && ((up >> (tx - 1)) & 1u);
        const bool NEf = (tx < 31) && ((up >> (tx + 1)) & 1u);
        if (Nf) {
            if (!(Wf && NWf)) uniteS(sl, t, t - 32);
        } else {
            if (NWf && !Wf) uniteS(sl, t, t - 33);
            if (NEf && !Ef) uniteS(sl, t, t - 31);
        }
    }
    __syncthreads();

    int lab;
    if (fg) {
        const int r = findRootS(sl, t);
        lab = b * HW + (((blockIdx.y << 5) + (r >> 5)) << 10)
                     + (blockIdx.x << 5) + (r & 31);
        if (r == t) d_counts[g] = 0;   // zero only potential count slots
    } else {
        lab = g | 0x80000000;
    }
    d_labels[g] = lab;

    if (blockIdx.x == 0 && blockIdx.y == 0 && blockIdx.z == 0 && t < BATCH)
        d_winner[t] = 0ULL;
}

// ---------------- kernel 2: merge across tile borders -----------------------
__global__ void k_border() {
    const int perB = 2 * 31 * 1024;
    int idx = blockIdx.x * blockDim.x + threadIdx.x;
    if (idx >= BATCH * perB) return;
    const int b = idx / perB;
    int j = idx - b * perB;
    const int base = b * HW;

    if (j < 31 * 1024) {
        // horizontal tile boundary rows 32,64,...,992
        const int r = 32 * (1 + (j >> 10));
        const int c = j & 1023;
        const int p = base + r * W + c;
        const int lp = d_labels[p];
        if (lp < 0) return;
        const int up = p - W;
        int ln = d_labels[up];
        if (ln >= 0) uniteG(lp, ln);
        if (c > 0)     { ln = d_labels[up - 1]; if (ln >= 0) uniteG(lp, ln); }
        if (c < W - 1) { ln = d_labels[up + 1]; if (ln >= 0) uniteG(lp, ln); }
    } else {
        // vertical tile boundary cols 32,64,...,992
        j -= 31 * 1024;
        const int c = 32 * (1 + (j >> 10));
        const int r = j & 1023;
        const int p = base + r * W + c;
        const int lp = d_labels[p];
        if (lp < 0) return;
        const int lf = p - 1;
        int ln = d_labels[lf];
        if (ln >= 0) uniteG(lp, ln);
        if (r > 0)     { ln = d_labels[lf - W]; if (ln >= 0) uniteG(lp, ln); }
        if (r < H - 1) { ln = d_labels[lf + W]; if (ln >= 0) uniteG(lp, ln); }
    }
}

// ---------------- kernel 3: per-tile hash count + compress + winner ---------
// Block = one 32x32 tile. Distinct tile labels (<=512) hashed in shared; each
// distinct label chased once to the global root with FULL path compression
// (forest is static now; compression stores are idempotent true roots). The
// running atomicAdd partial feeds the winner key: the chronologically-last add
// per root emits the exact final count, all partials are <= final, so the max
// key over all blocks = (max count, min root) with jnp.argmax tie-breaking.
#define HSLOTS 1024
__global__ __launch_bounds__(1024) void k_count() {
    __shared__ int hkey[HSLOTS];
    __shared__ int hcnt[HSLOTS];
    __shared__ unsigned long long blockmax;

    const int tx = threadIdx.x, ty = threadIdx.y;
    const int tid = (ty << 5) | tx;
    const int b = blockIdx.z;
    const int row = (blockIdx.y << 5) + ty;
    const int col = (blockIdx.x << 5) + tx;
    const int g = b * HW + row * W + col;

    hkey[tid] = -1;
    hcnt[tid] = 0;
    if (tid == 0) blockmax = 0ULL;
    __syncthreads();

    const int lab = d_labels[g];
    if (lab >= 0) {
        unsigned h = ((unsigned)lab * 2654435761u) >> 22;
        for (;;) {
            const int slot = h & (HSLOTS - 1);
            int k = atomicCAS(&hkey[slot], -1, lab);
            if (k == -1 || k == lab) { atomicAdd(&hcnt[slot], 1); break; }
            ++h;
        }
    }
    __syncthreads();

    const int slotkey = hkey[tid];
    if (slotkey >= 0) {
        // chase to root
        int r = slotkey;
        int pc = d_labels[r];
        while (pc != r) { r = pc; pc = d_labels[r]; }
        // full path compression: every tile-label entry ends pointing at root
        int xx = slotkey;
        while (xx != r) { int nxt = d_labels[xx]; d_labels[xx] = r; xx = nxt; }

        const int cnt = hcnt[tid];
        const int total = atomicAdd(&d_counts[r], cnt) + cnt;
        const unsigned long long key =
            ((unsigned long long)(unsigned)total << 32)
            | (unsigned long long)(0xFFFFFFFFu - (unsigned)r);
        atomicMax(&blockmax, key);
    }
    __syncthreads();

    if (tid == 0 && blockmax != 0ULL) {
        unsigned long long cur = *(volatile unsigned long long*)&d_winner[b];
        if (blockmax > cur) atomicMax(&d_winner[b], blockmax);
    }
}

// ---------------- kernel 4: masked output -----------------------------------
// Per-pixel label -> tile root; d_labels[tile root] is compressed to the final
// root by k3 (roots map to themselves), so one extra L2-resident lookup gives
// the final root. Hot lookup set ~2MB -> L2 hits with high MLP.
__global__ void k_write(const float* __restrict__ x, float* __restrict__ out) {
    const int i = blockIdx.x * blockDim.x + threadIdx.x;   // over NPIX/4
    const int p4 = i << 2;
    const int b = p4 >> 20;                                // HW = 2^20
    const int p = p4 & (HW - 1);

    const unsigned long long wk = d_winner[b];
    // no fg -> wk==0 -> wroot=-1 matches nothing (bg labels in [0x80000000,..))
    const int wroot = (int)(0xFFFFFFFFu - (unsigned)(wk & 0xFFFFFFFFu));

    const int4 lab = ((const int4*)d_labels)[i];
    const bool m0 = (lab.x >= 0) && (d_labels[lab.x] == wroot);
    const bool m1 = (lab.y >= 0) && (d_labels[lab.y] == wroot);
    const bool m2 = (lab.z >= 0) && (d_labels[lab.z] == wroot);
    const bool m3 = (lab.w >= 0) && (d_labels[lab.w] == wroot);

    const float* xb = x + (size_t)b * 2 * HW;
    const float4 v0 = *(const float4*)(xb + p);
    const float4 v1 = *(const float4*)(xb + HW + p);

    float4 o0, o1;
    o0.x = m0 ? v0.x : 0.0f;
    o0.y = m1 ? v0.y : 0.0f;
    o0.z = m2 ? v0.z : 0.0f;
    o0.w = m3 ? v0.w : 0.0f;
    o1.x = m0 ? v1.x : 0.0f;
    o1.y = m1 ? v1.y : 0.0f;
    o1.z = m2 ? v1.z : 0.0f;
    o1.w = m3 ? v1.w : 0.0f;

    float* ob = out + (size_t)b * 2 * HW;
    *(float4*)(ob + p) = o0;
    *(float4*)(ob + HW + p) = o1;
}

// ---------------- launcher --------------------------------------------------
extern "C" void kernel_launch(void* const* d_in, const int* in_sizes, int n_in,
                              void* d_out, int out_size) {
    const float* x = (const float*)d_in[0];
    float* out = (float*)d_out;

    dim3 blk(32, 32);
    dim3 grd(W / 32, H / 32, BATCH);

    k_init_local<<<grd, blk>>>(x);

    const int nb = BATCH * 2 * 31 * 1024;
    k_border<<<(nb + 255) / 256, 256>>>();

    k_count<<<grd, blk>>>();

    k_write<<<(NPIX / 4) / 256, 256>>>(x, out);
}

// round 6
// speedup vs baseline: 1.2871x; 1.0535x over previous
#include <cuda_runtime.h>
#include <stdint.h>

#define BATCH 16
#define H 1024
#define W 1024
#define HW (H*W)            // 1<<20
#define NPIX (BATCH*HW)
#define BGLAB 0xFFFFu

// ---------------- scratch (static device globals; no allocs) ----------------
// d_label16[g]: tile-local root id (0..1023) for fg pixels, 0xFFFF for bg.
// d_labels:     union-find parent store, ONLY tile-root entries are ever
//               initialized/read/written (sparse); k1 re-inits them each run.
__device__ unsigned short d_label16[NPIX];
__device__ int d_labels[NPIX];
__device__ int d_counts[NPIX];
__device__ unsigned long long d_winner[BATCH];

// reconstruct global index of a tile-local root id v inside tile
// (rowbase, colbase) of batch-base `base`
__device__ __forceinline__ int recon(int base, int rowbase, int colbase, int v) {
    return base + ((rowbase + (v >> 5)) << 10) + colbase + (v & 31);
}

// ---------------- shared-memory union-find (min-index roots) ----------------
__device__ __forceinline__ int findRootS(int* L, int x) {
    int p = L[x];
    while (p != x) { x = p; p = L[x]; }
    return p;
}
__device__ __forceinline__ void uniteS(int* L, int a, int b) {
    a = findRootS(L, a);
    b = findRootS(L, b);
    while (a != b) {
        if (a < b) { int t = a; a = b; b = t; }
        int old = atomicMin(&L[a], b);
        if (old == a) a = b;
        else a = old;
    }
}

// ---------------- global union-find with path halving -----------------------
// All writes are atomicMin of an in-component ancestor: monotone decreasing,
// race-safe alongside concurrent unions. Min-index roots == reference's
// min-propagation fixed point (labels AND argmax tie-break identical).
__device__ __forceinline__ int findRootH(int x) {
    int p = d_labels[x];
    while (p != x) {
        int gp = d_labels[p];
        if (gp != p) atomicMin(&d_labels[x], gp);
        x = p; p = gp;
    }
    return x;
}
__device__ __forceinline__ void uniteG(int a, int b) {
    a = findRootH(a);
    b = findRootH(b);
    while (a != b) {
        if (a < b) { int t = a; a = b; b = t; }
        int old = atomicMin(&d_labels[a], b);
        if (old == a) a = b;
        else a = old;
    }
}

// ---------------- kernel 1: fg + run-based tile-local CC --------------------
__global__ __launch_bounds__(1024) void k_init_local(const float* __restrict__ x) {
    __shared__ int sl[1024];
    __shared__ unsigned smask[32];

    const int tx = threadIdx.x, ty = threadIdx.y;
    const int t = (ty << 5) | tx;
    const int b = blockIdx.z;
    const int row = (blockIdx.y << 5) + ty;
    const int col = (blockIdx.x << 5) + tx;
    const int p = row * W + col;
    const int g = b * HW + p;

    const float* xb = x + (size_t)b * 2 * HW;
    const int fg = (xb[HW + p] > xb[p]) ? 1 : 0;   // argmax 2 classes, tie->0

    const unsigned rowmask = __ballot_sync(0xFFFFFFFFu, fg);
    if (tx == 0) smask[ty] = rowmask;

    int node = t;
    if (fg) {
        const unsigned runstarts = rowmask & ~(rowmask << 1);
        const unsigned below = runstarts & ((2u << tx) - 1u);
        node = (ty << 5) | (31 - __clz(below));    // run leader
    }
    sl[t] = node;
    __syncthreads();

    if (fg && ty > 0) {
        const unsigned up = smask[ty - 1];
        const bool Wf  = (tx > 0)  && ((rowmask >> (tx - 1)) & 1u);
        const bool Ef  = (tx < 31) && ((rowmask >> (tx + 1)) & 1u);
        const bool Nf  = (up >> tx) & 1u;
        const bool NWf = (tx > 0)  && ((up >> (tx - 1)) & 1u);
        const bool NEf = (tx < 31) && ((up >> (tx + 1)) & 1u);
        if (Nf) {
            if (!(Wf && NWf)) uniteS(sl, t, t - 32);
        } else {
            if (NWf && !Wf) uniteS(sl, t, t - 33);
            if (NEf && !Ef) uniteS(sl, t, t - 31);
        }
    }
    __syncthreads();

    if (fg) {
        const int r = findRootS(sl, t);
        d_label16[g] = (unsigned short)r;
        if (r == t) { d_labels[g] = g; d_counts[g] = 0; }   // sparse init
    } else {
        d_label16[g] = (unsigned short)BGLAB;
    }

    if (blockIdx.x == 0 && blockIdx.y == 0 && blockIdx.z == 0 && t < BATCH)
        d_winner[t] = 0ULL;
}

// ---------------- kernel 2: run-filtered cross-tile border merges -----------
// Warps align exactly with 32-wide tile edges, so the k1 run-adjacency filter
// applies; corner lanes (where the in-tile covering link doesn't exist) fall
// back to unconditional unions via forced-false flags.
__global__ void k_border() {
    const int perB = 2 * 31 * 1024;
    const int idx = blockIdx.x * blockDim.x + threadIdx.x;
    if (idx >= BATCH * perB) return;
    const int b = idx / perB;
    int j = idx - b * perB;
    const int base = b * HW;

    if (j < 31 * 1024) {
        // horizontal boundary rows 32,64,...,992; lane = column & 31
        const int r = 32 * (1 + (j >> 10));
        const int c = j & 1023;
        const int lane = c & 31;
        const int p = base + r * W + c;

        const int v  = d_label16[p];
        const int vn = d_label16[p - W];
        int nwv = __shfl_up_sync(0xFFFFFFFFu, vn, 1);
        int nev = __shfl_down_sync(0xFFFFFFFFu, vn, 1);
        if (lane == 0)  nwv = (c > 0)     ? (int)d_label16[p - W - 1] : (int)BGLAB;
        if (lane == 31) nev = (c < 1023)  ? (int)d_label16[p - W + 1] : (int)BGLAB;
        const unsigned rowm = __ballot_sync(0xFFFFFFFFu, v != (int)BGLAB);
        const unsigned upm  = __ballot_sync(0xFFFFFFFFu, vn != (int)BGLAB);
        if (v == (int)BGLAB) return;

        const bool Wf  = lane > 0  && ((rowm >> (lane - 1)) & 1u);
        const bool Ef  = lane < 31 && ((rowm >> (lane + 1)) & 1u);
        const bool Nf  = (upm >> lane) & 1u;
        const bool NWf = nwv != (int)BGLAB;
        const bool NEf = nev != (int)BGLAB;

        const int lp = recon(base, r, c & ~31, v);
        if (Nf) {
            if (!(Wf && NWf)) uniteG(lp, recon(base, r - 32, c & ~31, vn));
        } else {
            if (NWf && !Wf) uniteG(lp, recon(base, r - 32, (c - 1) & ~31, nwv));
            if (NEf && !Ef) uniteG(lp, recon(base, r - 32, (c + 1) & ~31, nev));
        }
    } else {
        // vertical boundary cols 32,64,...,992; lane = row & 31
        j -= 31 * 1024;
        const int c = 32 * (1 + (j >> 10));
        const int r = j & 1023;
        const int lane = r & 31;
        const int p = base + r * W + c;

        const int v  = d_label16[p];
        const int wv = d_label16[p - 1];
        int nwv = __shfl_up_sync(0xFFFFFFFFu, wv, 1);
        int swv = __shfl_down_sync(0xFFFFFFFFu, wv, 1);
        if (lane == 0)  nwv = (r > 0)    ? (int)d_label16[p - W - 1] : (int)BGLAB;
        if (lane == 31) swv = (r < 1023) ? (int)d_label16[p + W - 1] : (int)BGLAB;
        const unsigned colm = __ballot_sync(0xFFFFFFFFu, v != (int)BGLAB);
        __syncwarp();
        if (v == (int)BGLAB) return;

        const bool Nf  = lane > 0  && ((colm >> (lane - 1)) & 1u);
        const bool Sf  = lane < 31 && ((colm >> (lane + 1)) & 1u);
        const bool Wf  = wv  != (int)BGLAB;
        const bool NWf = nwv != (int)BGLAB;
        const bool SWf = swv != (int)BGLAB;

        const int lp = recon(base, r & ~31, c, v);
        if (Wf) {
            if (!(Nf && NWf)) uniteG(lp, recon(base, r & ~31, c - 32, wv));
        } else {
            if (NWf && !Nf) uniteG(lp, recon(base, (r - 1) & ~31, c - 32, nwv));
            if (SWf && !Sf) uniteG(lp, recon(base, (r + 1) & ~31, c - 32, swv));
        }
    }
}

// ---------------- kernel 3: direct-index count + compress + winner ----------
// Block = one 32x32 tile. u16 labels are tile-local ids -> direct-indexed
// 1024-slot shared counter (no hashing). Slots with cnt>0 are exactly the
// tile roots: chase to global root with FULL path compression (forest static),
// accumulate, and feed the winner key. The chronologically-last atomicAdd per
// root emits its exact final count; all partials <= final, so max key over all
// blocks = (max count, min root) -- jnp.argmax tie-break preserved.
__global__ __launch_bounds__(1024) void k_count() {
    __shared__ int hcnt[1024];
    __shared__ unsigned long long blockmax;

    const int tid = (threadIdx.y << 5) | threadIdx.x;
    const int b = blockIdx.z;
    const int row = (blockIdx.y << 5) + threadIdx.y;
    const int col = (blockIdx.x << 5) + threadIdx.x;
    const int g = b * HW + row * W + col;
    const int base = b * HW;

    hcnt[tid] = 0;
    if (tid == 0) blockmax = 0ULL;
    __syncthreads();

    const int v = d_label16[g];
    if (v != (int)BGLAB) atomicAdd(&hcnt[v], 1);
    __syncthreads();

    const int cnt = hcnt[tid];
    if (cnt > 0) {
        const int node = recon(base, blockIdx.y << 5, blockIdx.x << 5, tid);
        // chase
        int r = node, pc = d_labels[node];
        while (pc != r) { r = pc; pc = d_labels[r]; }
        // full path compression (idempotent true-root stores; forest static)
        int xx = node;
        while (xx != r) { int nxt = d_labels[xx]; d_labels[xx] = r; xx = nxt; }

        const int total = atomicAdd(&d_counts[r], cnt) + cnt;
        const unsigned long long key =
            ((unsigned long long)(unsigned)total << 32)
            | (unsigned long long)(0xFFFFFFFFu - (unsigned)r);
        atomicMax(&blockmax, key);
    }
    __syncthreads();

    if (tid == 0 && blockmax != 0ULL) {
        unsigned long long cur = *(volatile unsigned long long*)&d_winner[b];
        if (blockmax > cur) atomicMax(&d_winner[b], blockmax);
    }
}

// ---------------- kernel 4: masked output -----------------------------------
// u16 label -> reconstructed tile root -> one L2-resident d_labels lookup
// (compressed to final root by k3).
__global__ void k_write(const float* __restrict__ x, float* __restrict__ out) {
    const int i = blockIdx.x * blockDim.x + threadIdx.x;   // over NPIX/4
    const int p4 = i << 2;
    const int b = p4 >> 20;                                // HW = 2^20
    const int p = p4 & (HW - 1);

    const unsigned long long wk = d_winner[b];
    const int wroot = (int)(0xFFFFFFFFu - (unsigned)(wk & 0xFFFFFFFFu)); // no fg -> -1

    const ushort4 lv = ((const ushort4*)d_label16)[i];
    const int base = b * HW;
    const int rowbase = (p >> 10) & ~31;
    const int colbase = p & 0x3E0;          // (p & 1023) & ~31

    const bool m0 = (lv.x != BGLAB) && (d_labels[recon(base, rowbase, colbase, lv.x)] == wroot);
    const bool m1 = (lv.y != BGLAB) && (d_labels[recon(base, rowbase, colbase, lv.y)] == wroot);
    const bool m2 = (lv.z != BGLAB) && (d_labels[recon(base, rowbase, colbase, lv.z)] == wroot);
    const bool m3 = (lv.w != BGLAB) && (d_labels[recon(base, rowbase, colbase, lv.w)] == wroot);

    const float* xb = x + (size_t)b * 2 * HW;
    const float4 v0 = *(const float4*)(xb + p);
    const float4 v1 = *(const float4*)(xb + HW + p);

    float4 o0, o1;
    o0.x = m0 ? v0.x : 0.0f;
    o0.y = m1 ? v0.y : 0.0f;
    o0.z = m2 ? v0.z : 0.0f;
    o0.w = m3 ? v0.w : 0.0f;
    o1.x = m0 ? v1.x : 0.0f;
    o1.y = m1 ? v1.y : 0.0f;
    o1.z = m2 ? v1.z : 0.0f;
    o1.w = m3 ? v1.w : 0.0f;

    float* ob = out + (size_t)b * 2 * HW;
    *(float4*)(ob + p) = o0;
    *(float4*)(ob + HW + p) = o1;
}

// ---------------- launcher --------------------------------------------------
extern "C" void kernel_launch(void* const* d_in, const int* in_sizes, int n_in,
                              void* d_out, int out_size) {
    const float* x = (const float*)d_in[0];
    float* out = (float*)d_out;

    dim3 blk(32, 32);
    dim3 grd(W / 32, H / 32, BATCH);

    k_init_local<<<grd, blk>>>(x);

    const int nb = BATCH * 2 * 31 * 1024;
    k_border<<<(nb + 255) / 256, 256>>>();

    k_count<<<grd, blk>>>();

    k_write<<<(NPIX / 4) / 256, 256>>>(x, out);
}

// round 7
// speedup vs baseline: 2.0701x; 1.6083x over previous
#include <cuda_runtime.h>
#include <stdint.h>

#define BATCH 16
#define H 1024
#define W 1024
#define HW (H*W)            // 1<<20
#define NPIX (BATCH*HW)
#define BGLAB 0xFFFFu

// ---------------- scratch (static device globals; no allocs) ----------------
// d_label16[g]: tile-local root id (0..1023) for fg pixels, 0xFFFF for bg.
// d_labels:     union-find parent store; ONLY tile-root entries are ever
//               initialized/read/written (sparse).
__device__ unsigned short d_label16[NPIX];
__device__ int d_labels[NPIX];
__device__ int d_counts[NPIX];
__device__ unsigned long long d_winner[BATCH];

// reconstruct global index of tile-local id v in tile (rowbase,colbase), batch base
__device__ __forceinline__ int recon(int base, int rowbase, int colbase, int v) {
    return base + ((rowbase + (v >> 5)) << 10) + colbase + (v & 31);
}

// ---------------- shared-memory union-find (min-index roots) ----------------
__device__ __forceinline__ int findRootS(int* L, int x) {
    int p = L[x];
    while (p != x) { x = p; p = L[x]; }
    return p;
}
__device__ __forceinline__ void uniteS(int* L, int a, int b) {
    a = findRootS(L, a);
    b = findRootS(L, b);
    while (a != b) {
        if (a < b) { int t = a; a = b; b = t; }
        int old = atomicMin(&L[a], b);
        if (old == a) a = b;
        else a = old;
    }
}

// ---------------- global union-find with path halving -----------------------
__device__ __forceinline__ int findRootH(int x) {
    int p = d_labels[x];
    while (p != x) {
        int gp = d_labels[p];
        if (gp != p) atomicMin(&d_labels[x], gp);
        x = p; p = gp;
    }
    return x;
}
__device__ __forceinline__ void uniteG(int a, int b) {
    a = findRootH(a);
    b = findRootH(b);
    while (a != b) {
        if (a < b) { int t = a; a = b; b = t; }
        int old = atomicMin(&d_labels[a], b);
        if (old == a) a = b;
        else a = old;
    }
}

// ---------------- kernel 1: fg + run-based tile-local CC (256 thr) ----------
// Tile 32x32, 256 threads, 4 consecutive pixels per thread (float4 loads).
// Thread -> row = tid>>3, cols 4*(tid&7)..+3. A warp covers 4 rows; row masks
// are assembled in-register by a 3-step shfl_xor OR butterfly over the 8 lanes
// of each row group, then published to shared for the cross-row union filter:
//   N fg:            union(t, N)  unless (W fg && NW fg)
//   N bg && NW fg:   union(t, NW) unless W fg
//   N bg && NE fg:   union(t, NE) unless E fg
__global__ __launch_bounds__(256) void k_init_local(const float* __restrict__ x) {
    __shared__ int sl[1024];
    __shared__ unsigned smask[32];

    const int tid = threadIdx.x;
    const int row = tid >> 3;           // 0..31
    const int col4 = (tid & 7) << 2;    // 0,4,...,28
    const int b = blockIdx.z;
    const int grow = (blockIdx.y << 5) + row;
    const int gcol = (blockIdx.x << 5) + col4;
    const int p = grow * W + gcol;
    const int gbase = b * HW;
    const int g = gbase + p;

    const float* xb = x + (size_t)b * 2 * HW;
    const float4 a0 = *(const float4*)(xb + p);
    const float4 a1 = *(const float4*)(xb + HW + p);

    unsigned nib = (a1.x > a0.x ? 1u : 0u) | (a1.y > a0.y ? 2u : 0u)
                 | (a1.z > a0.z ? 4u : 0u) | (a1.w > a0.w ? 8u : 0u);

    // OR-butterfly within 8-lane row groups -> full 32-bit row mask
    unsigned m = nib << (col4 & 31);
    m |= __shfl_xor_sync(0xFFFFFFFFu, m, 1);
    m |= __shfl_xor_sync(0xFFFFFFFFu, m, 2);
    m |= __shfl_xor_sync(0xFFFFFFFFu, m, 4);
    if ((tid & 7) == 0) smask[row] = m;

    // run leaders for the 4 pixels (in-register, needs only m)
    const unsigned runstarts = m & ~(m << 1);
    const int r32 = row << 5;
    int4 nodes;
    {
        int n0 = r32 + col4, n1 = n0 + 1, n2 = n0 + 2, n3 = n0 + 3;
        if (nib & 1u) n0 = r32 + (31 - __clz(runstarts & ((2u << (col4    )) - 1u)));
        if (nib & 2u) n1 = r32 + (31 - __clz(runstarts & ((2u << (col4 + 1)) - 1u)));
        if (nib & 4u) n2 = r32 + (31 - __clz(runstarts & ((2u << (col4 + 2)) - 1u)));
        if (nib & 8u) n3 = r32 + (31 - __clz(runstarts & ((2u << (col4 + 3)) - 1u)));
        nodes = make_int4(n0, n1, n2, n3);
    }
    *(int4*)&sl[r32 + col4] = nodes;
    __syncthreads();

    if (row > 0 && nib) {
        const unsigned up = smask[row - 1];
        #pragma unroll
        for (int j = 0; j < 4; ++j) {
            if (!((nib >> j) & 1u)) continue;
            const int c = col4 + j;
            const int t = r32 + c;
            const bool Wf  = (c > 0)  && ((m >> (c - 1)) & 1u);
            const bool Ef  = (c < 31) && ((m >> (c + 1)) & 1u);
            const bool Nf  = (up >> c) & 1u;
            const bool NWf = (c > 0)  && ((up >> (c - 1)) & 1u);
            const bool NEf = (c < 31) && ((up >> (c + 1)) & 1u);
            if (Nf) {
                if (!(Wf && NWf)) uniteS(sl, t, t - 32);
            } else {
                if (NWf && !Wf) uniteS(sl, t, t - 33);
                if (NEf && !Ef) uniteS(sl, t, t - 31);
            }
        }
    }
    __syncthreads();

    ushort4 outl;
    {
        unsigned short v[4];
        #pragma unroll
        for (int j = 0; j < 4; ++j) {
            if ((nib >> j) & 1u) {
                const int t = r32 + col4 + j;
                const int r = findRootS(sl, t);
                v[j] = (unsigned short)r;
                if (r == t) { d_labels[g + j] = g + j; d_counts[g + j] = 0; }
            } else {
                v[j] = (unsigned short)BGLAB;
            }
        }
        outl = make_ushort4(v[0], v[1], v[2], v[3]);
    }
    *(ushort4*)&d_label16[g] = outl;

    if (blockIdx.x == 0 && blockIdx.y == 0 && blockIdx.z == 0 && tid < BATCH)
        d_winner[tid] = 0ULL;
}

// ---------------- kernel 2: run-filtered cross-tile border merges -----------
__global__ void k_border() {
    const int perB = 2 * 31 * 1024;
    const int idx = blockIdx.x * blockDim.x + threadIdx.x;
    if (idx >= BATCH * perB) return;
    const int b = idx / perB;
    int j = idx - b * perB;
    const int base = b * HW;

    if (j < 31 * 1024) {
        // horizontal boundary rows 32,64,...,992; lane = column & 31
        const int r = 32 * (1 + (j >> 10));
        const int c = j & 1023;
        const int lane = c & 31;
        const int p = base + r * W + c;

        const int v  = d_label16[p];
        const int vn = d_label16[p - W];
        int nwv = __shfl_up_sync(0xFFFFFFFFu, vn, 1);
        int nev = __shfl_down_sync(0xFFFFFFFFu, vn, 1);
        if (lane == 0)  nwv = (c > 0)    ? (int)d_label16[p - W - 1] : (int)BGLAB;
        if (lane == 31) nev = (c < 1023) ? (int)d_label16[p - W + 1] : (int)BGLAB;
        const unsigned rowm = __ballot_sync(0xFFFFFFFFu, v != (int)BGLAB);
        const unsigned upm  = __ballot_sync(0xFFFFFFFFu, vn != (int)BGLAB);
        if (v == (int)BGLAB) return;

        const bool Wf  = lane > 0  && ((rowm >> (lane - 1)) & 1u);
        const bool Ef  = lane < 31 && ((rowm >> (lane + 1)) & 1u);
        const bool Nf  = (upm >> lane) & 1u;
        const bool NWf = nwv != (int)BGLAB;
        const bool NEf = nev != (int)BGLAB;

        const int lp = recon(base, r, c & ~31, v);
        if (Nf) {
            if (!(Wf && NWf)) uniteG(lp, recon(base, r - 32, c & ~31, vn));
        } else {
            if (NWf && !Wf) uniteG(lp, recon(base, r - 32, (c - 1) & ~31, nwv));
            if (NEf && !Ef) uniteG(lp, recon(base, r - 32, (c + 1) & ~31, nev));
        }
    } else {
        // vertical boundary cols 32,64,...,992; lane = row & 31
        j -= 31 * 1024;
        const int c = 32 * (1 + (j >> 10));
        const int r = j & 1023;
        const int lane = r & 31;
        const int p = base + r * W + c;

        const int v  = d_label16[p];
        const int wv = d_label16[p - 1];
        int nwv = __shfl_up_sync(0xFFFFFFFFu, wv, 1);
        int swv = __shfl_down_sync(0xFFFFFFFFu, wv, 1);
        if (lane == 0)  nwv = (r > 0)    ? (int)d_label16[p - W - 1] : (int)BGLAB;
        if (lane == 31) swv = (r < 1023) ? (int)d_label16[p + W - 1] : (int)BGLAB;
        const unsigned colm = __ballot_sync(0xFFFFFFFFu, v != (int)BGLAB);
        __syncwarp();
        if (v == (int)BGLAB) return;

        const bool Nf  = lane > 0  && ((colm >> (lane - 1)) & 1u);
        const bool Sf  = lane < 31 && ((colm >> (lane + 1)) & 1u);
        const bool Wf  = wv  != (int)BGLAB;
        const bool NWf = nwv != (int)BGLAB;
        const bool SWf = swv != (int)BGLAB;

        const int lp = recon(base, r & ~31, c, v);
        if (Wf) {
            if (!(Nf && NWf)) uniteG(lp, recon(base, r & ~31, c - 32, wv));
        } else {
            if (NWf && !Nf) uniteG(lp, recon(base, (r - 1) & ~31, c - 32, nwv));
            if (SWf && !Sf) uniteG(lp, recon(base, (r + 1) & ~31, c - 32, swv));
        }
    }
}

// ---------------- kernel 3: direct-index count + compress + winner (256 thr)-
// Block = one 32x32 tile, 4 consecutive pixels/thread (ushort4 loads).
// Slots with cnt>0 are exactly the tile roots: chase to global root with FULL
// path compression (forest static; stores are idempotent true roots),
// accumulate, feed winner key. Chronologically-last atomicAdd per root carries
// its exact final count; all partials <= final, so the global max key equals
// (max count, min root) -- jnp.argmax tie-break preserved.
__global__ __launch_bounds__(256) void k_count() {
    __shared__ int hcnt[1024];
    __shared__ unsigned long long blockmax;

    const int tid = threadIdx.x;
    const int row = tid >> 3;
    const int col4 = (tid & 7) << 2;
    const int b = blockIdx.z;
    const int base = b * HW;
    const int g = base + (((blockIdx.y << 5) + row) << 10) + (blockIdx.x << 5) + col4;

    *(int4*)&hcnt[tid << 2] = make_int4(0, 0, 0, 0);
    if (tid == 0) blockmax = 0ULL;
    __syncthreads();

    const ushort4 lv = *(const ushort4*)&d_label16[g];
    if (lv.x != BGLAB) atomicAdd(&hcnt[lv.x], 1);
    if (lv.y != BGLAB) atomicAdd(&hcnt[lv.y], 1);
    if (lv.z != BGLAB) atomicAdd(&hcnt[lv.z], 1);
    if (lv.w != BGLAB) atomicAdd(&hcnt[lv.w], 1);
    __syncthreads();

    const int4 cnts = *(const int4*)&hcnt[tid << 2];
    const int cv[4] = {cnts.x, cnts.y, cnts.z, cnts.w};
    unsigned long long localmax = 0ULL;
    #pragma unroll
    for (int j = 0; j < 4; ++j) {
        const int cnt = cv[j];
        if (cnt > 0) {
            const int node = recon(base, blockIdx.y << 5, blockIdx.x << 5, (tid << 2) + j);
            int r = node, pc = d_labels[node];
            while (pc != r) { r = pc; pc = d_labels[r]; }
            int xx = node;
            while (xx != r) { int nxt = d_labels[xx]; d_labels[xx] = r; xx = nxt; }

            const int total = atomicAdd(&d_counts[r], cnt) + cnt;
            const unsigned long long key =
                ((unsigned long long)(unsigned)total << 32)
                | (unsigned long long)(0xFFFFFFFFu - (unsigned)r);
            if (key > localmax) localmax = key;
        }
    }
    if (localmax) atomicMax(&blockmax, localmax);
    __syncthreads();

    if (tid == 0 && blockmax != 0ULL) {
        unsigned long long cur = *(volatile unsigned long long*)&d_winner[b];
        if (blockmax > cur) atomicMax(&d_winner[b], blockmax);
    }
}

// ---------------- kernel 4: masked output -----------------------------------
__global__ void k_write(const float* __restrict__ x, float* __restrict__ out) {
    const int i = blockIdx.x * blockDim.x + threadIdx.x;   // over NPIX/4
    const int p4 = i << 2;
    const int b = p4 >> 20;                                // HW = 2^20
    const int p = p4 & (HW - 1);

    const unsigned long long wk = d_winner[b];
    const int wroot = (int)(0xFFFFFFFFu - (unsigned)(wk & 0xFFFFFFFFu)); // no fg -> -1

    const ushort4 lv = ((const ushort4*)d_label16)[i];
    const int base = b * HW;
    const int rowbase = (p >> 10) & ~31;
    const int colbase = p & 0x3E0;

    const bool m0 = (lv.x != BGLAB) && (d_labels[recon(base, rowbase, colbase, lv.x)] == wroot);
    const bool m1 = (lv.y != BGLAB) && (d_labels[recon(base, rowbase, colbase, lv.y)] == wroot);
    const bool m2 = (lv.z != BGLAB) && (d_labels[recon(base, rowbase, colbase, lv.z)] == wroot);
    const bool m3 = (lv.w != BGLAB) && (d_labels[recon(base, rowbase, colbase, lv.w)] == wroot);

    const float* xb = x + (size_t)b * 2 * HW;
    const float4 v0 = *(const float4*)(xb + p);
    const float4 v1 = *(const float4*)(xb + HW + p);

    float4 o0, o1;
    o0.x = m0 ? v0.x : 0.0f;
    o0.y = m1 ? v0.y : 0.0f;
    o0.z = m2 ? v0.z : 0.0f;
    o0.w = m3 ? v0.w : 0.0f;
    o1.x = m0 ? v1.x : 0.0f;
    o1.y = m1 ? v1.y : 0.0f;
    o1.z = m2 ? v1.z : 0.0f;
    o1.w = m3 ? v1.w : 0.0f;

    float* ob = out + (size_t)b * 2 * HW;
    *(float4*)(ob + p) = o0;
    *(float4*)(ob + HW + p) = o1;
}

// ---------------- launcher --------------------------------------------------
extern "C" void kernel_launch(void* const* d_in, const int* in_sizes, int n_in,
                              void* d_out, int out_size) {
    const float* x = (const float*)d_in[0];
    float* out = (float*)d_out;

    dim3 grd(W / 32, H / 32, BATCH);

    k_init_local<<<grd, 256>>>(x);

    const int nb = BATCH * 2 * 31 * 1024;
    k_border<<<(nb + 255) / 256, 256>>>();

    k_count<<<grd, 256>>>();

    k_write<<<(NPIX / 4) / 256, 256>>>(x, out);
}

// round 8
// speedup vs baseline: 2.2203x; 1.0726x over previous
#include <cuda_runtime.h>
#include <stdint.h>

#define BATCH 16
#define H 1024
#define W 1024
#define HW (H*W)            // 1<<20
#define NPIX (BATCH*HW)
#define BGLAB 0xFFFFu

// ---------------- scratch (static device globals; no allocs) ----------------
// d_label16[g]: tile-local root id (0..1023) for fg pixels, 0xFFFF for bg.
// d_labels:     union-find parent store; ONLY tile-root entries are ever
//               initialized/read/written (sparse).
__device__ unsigned short d_label16[NPIX];
__device__ int d_labels[NPIX];
__device__ int d_counts[NPIX];
__device__ unsigned long long d_winner[BATCH];

// reconstruct global index of tile-local id v in tile (rowbase,colbase), batch base
__device__ __forceinline__ int recon(int base, int rowbase, int colbase, int v) {
    return base + ((rowbase + (v >> 5)) << 10) + colbase + (v & 31);
}

// ---------------- shared-memory union-find (min-index roots) ----------------
// find with path halving: halving writes are atomicMin of an in-component
// ancestor (monotone decreasing) -> race-safe alongside concurrent unions.
__device__ __forceinline__ int findRootSH(int* L, int x) {
    int p = L[x];
    while (p != x) {
        int gp = L[p];
        if (gp != p) atomicMin(&L[x], gp);
        x = p; p = gp;
    }
    return x;
}
__device__ __forceinline__ int findRootS(int* L, int x) {   // read-only chase
    int p = L[x];
    while (p != x) { x = p; p = L[x]; }
    return p;
}
__device__ __forceinline__ void uniteS(int* L, int a, int b) {
    a = findRootSH(L, a);
    b = findRootSH(L, b);
    while (a != b) {
        if (a < b) { int t = a; a = b; b = t; }
        int old = atomicMin(&L[a], b);
        if (old == a) a = b;
        else a = old;
    }
}

// ---------------- global union-find with path halving -----------------------
__device__ __forceinline__ int findRootH(int x) {
    int p = d_labels[x];
    while (p != x) {
        int gp = d_labels[p];
        if (gp != p) atomicMin(&d_labels[x], gp);
        x = p; p = gp;
    }
    return x;
}
__device__ __forceinline__ void uniteG(int a, int b) {
    a = findRootH(a);
    b = findRootH(b);
    while (a != b) {
        if (a < b) { int t = a; a = b; b = t; }
        int old = atomicMin(&d_labels[a], b);
        if (old == a) a = b;
        else a = old;
    }
}

// ---------------- kernel 1: fg + run-based tile-local CC (256 thr) ----------
// Tile 32x32, 256 threads, 4 consecutive pixels per thread (float4 loads).
// Row masks assembled in-register by a shfl_xor OR butterfly; run leaders by
// bit tricks; cross-row unions filtered to ~1 per run-adjacency; then ONLY
// run leaders chase to the root (+compress), and every pixel resolves with a
// single shared read of its leader's entry.
__global__ __launch_bounds__(256) void k_init_local(const float* __restrict__ x) {
    __shared__ int sl[1024];
    __shared__ unsigned smask[32];

    const int tid = threadIdx.x;
    const int row = tid >> 3;           // 0..31
    const int col4 = (tid & 7) << 2;    // 0,4,...,28
    const int b = blockIdx.z;
    const int grow = (blockIdx.y << 5) + row;
    const int gcol = (blockIdx.x << 5) + col4;
    const int p = grow * W + gcol;
    const int g = b * HW + p;

    const float* xb = x + (size_t)b * 2 * HW;
    const float4 a0 = *(const float4*)(xb + p);
    const float4 a1 = *(const float4*)(xb + HW + p);

    unsigned nib = (a1.x > a0.x ? 1u : 0u) | (a1.y > a0.y ? 2u : 0u)
                 | (a1.z > a0.z ? 4u : 0u) | (a1.w > a0.w ? 8u : 0u);

    // OR-butterfly within 8-lane row groups -> full 32-bit row mask
    unsigned m = nib << (col4 & 31);
    m |= __shfl_xor_sync(0xFFFFFFFFu, m, 1);
    m |= __shfl_xor_sync(0xFFFFFFFFu, m, 2);
    m |= __shfl_xor_sync(0xFFFFFFFFu, m, 4);
    if ((tid & 7) == 0) smask[row] = m;

    // run leaders for the 4 pixels
    const unsigned runstarts = m & ~(m << 1);
    const int r32 = row << 5;
    int n0 = r32 + col4, n1 = n0 + 1, n2 = n0 + 2, n3 = n0 + 3;
    if (nib & 1u) n0 = r32 + (31 - __clz(runstarts & ((2u << (col4    )) - 1u)));
    if (nib & 2u) n1 = r32 + (31 - __clz(runstarts & ((2u << (col4 + 1)) - 1u)));
    if (nib & 4u) n2 = r32 + (31 - __clz(runstarts & ((2u << (col4 + 2)) - 1u)));
    if (nib & 8u) n3 = r32 + (31 - __clz(runstarts & ((2u << (col4 + 3)) - 1u)));
    *(int4*)&sl[r32 + col4] = make_int4(n0, n1, n2, n3);
    __syncthreads();

    if (row > 0 && nib) {
        const unsigned up = smask[row - 1];
        #pragma unroll
        for (int j = 0; j < 4; ++j) {
            if (!((nib >> j) & 1u)) continue;
            const int c = col4 + j;
            const int t = r32 + c;
            const bool Wf  = (c > 0)  && ((m >> (c - 1)) & 1u);
            const bool Ef  = (c < 31) && ((m >> (c + 1)) & 1u);
            const bool Nf  = (up >> c) & 1u;
            const bool NWf = (c > 0)  && ((up >> (c - 1)) & 1u);
            const bool NEf = (c < 31) && ((up >> (c + 1)) & 1u);
            if (Nf) {
                if (!(Wf && NWf)) uniteS(sl, t, t - 32);
            } else {
                if (NWf && !Wf) uniteS(sl, t, t - 33);
                if (NEf && !Ef) uniteS(sl, t, t - 31);
            }
        }
    }
    __syncthreads();

    // leader-only resolution + compression; root leaders do the sparse init
    const int nodes[4] = {n0, n1, n2, n3};
    #pragma unroll
    for (int j = 0; j < 4; ++j) {
        if ((nib >> j) & 1u) {
            const int t = r32 + col4 + j;
            if (nodes[j] == t) {                     // run leader
                const int r = findRootS(sl, t);
                sl[t] = r;                           // compress (true root)
                if (r == t) { d_labels[g + j] = g + j; d_counts[g + j] = 0; }
            }
        }
    }
    __syncthreads();

    // per-pixel final label: one shared read of the leader entry
    ushort4 outl;
    {
        unsigned short v[4];
        #pragma unroll
        for (int j = 0; j < 4; ++j)
            v[j] = ((nib >> j) & 1u) ? (unsigned short)sl[nodes[j]]
                                     : (unsigned short)BGLAB;
        outl = make_ushort4(v[0], v[1], v[2], v[3]);
    }
    *(ushort4*)&d_label16[g] = outl;

    if (blockIdx.x == 0 && blockIdx.y == 0 && blockIdx.z == 0 && tid < BATCH)
        d_winner[tid] = 0ULL;
}

// ---------------- kernel 2: run-filtered cross-tile border merges -----------
__global__ void k_border() {
    const int perB = 2 * 31 * 1024;
    const int idx = blockIdx.x * blockDim.x + threadIdx.x;
    if (idx >= BATCH * perB) return;
    const int b = idx / perB;
    int j = idx - b * perB;
    const int base = b * HW;

    if (j < 31 * 1024) {
        // horizontal boundary rows 32,64,...,992; lane = column & 31
        const int r = 32 * (1 + (j >> 10));
        const int c = j & 1023;
        const int lane = c & 31;
        const int p = base + r * W + c;

        const int v  = d_label16[p];
        const int vn = d_label16[p - W];
        int nwv = __shfl_up_sync(0xFFFFFFFFu, vn, 1);
        int nev = __shfl_down_sync(0xFFFFFFFFu, vn, 1);
        if (lane == 0)  nwv = (c > 0)    ? (int)d_label16[p - W - 1] : (int)BGLAB;
        if (lane == 31) nev = (c < 1023) ? (int)d_label16[p - W + 1] : (int)BGLAB;
        const unsigned rowm = __ballot_sync(0xFFFFFFFFu, v != (int)BGLAB);
        const unsigned upm  = __ballot_sync(0xFFFFFFFFu, vn != (int)BGLAB);
        if (v == (int)BGLAB) return;

        const bool Wf  = lane > 0  && ((rowm >> (lane - 1)) & 1u);
        const bool Ef  = lane < 31 && ((rowm >> (lane + 1)) & 1u);
        const bool Nf  = (upm >> lane) & 1u;
        const bool NWf = nwv != (int)BGLAB;
        const bool NEf = nev != (int)BGLAB;

        const int lp = recon(base, r, c & ~31, v);
        if (Nf) {
            if (!(Wf && NWf)) uniteG(lp, recon(base, r - 32, c & ~31, vn));
        } else {
            if (NWf && !Wf) uniteG(lp, recon(base, r - 32, (c - 1) & ~31, nwv));
            if (NEf && !Ef) uniteG(lp, recon(base, r - 32, (c + 1) & ~31, nev));
        }
    } else {
        // vertical boundary cols 32,64,...,992; lane = row & 31
        j -= 31 * 1024;
        const int c = 32 * (1 + (j >> 10));
        const int r = j & 1023;
        const int lane = r & 31;
        const int p = base + r * W + c;

        const int v  = d_label16[p];
        const int wv = d_label16[p - 1];
        int nwv = __shfl_up_sync(0xFFFFFFFFu, wv, 1);
        int swv = __shfl_down_sync(0xFFFFFFFFu, wv, 1);
        if (lane == 0)  nwv = (r > 0)    ? (int)d_label16[p - W - 1] : (int)BGLAB;
        if (lane == 31) swv = (r < 1023) ? (int)d_label16[p + W - 1] : (int)BGLAB;
        const unsigned colm = __ballot_sync(0xFFFFFFFFu, v != (int)BGLAB);
        __syncwarp();
        if (v == (int)BGLAB) return;

        const bool Nf  = lane > 0  && ((colm >> (lane - 1)) & 1u);
        const bool Sf  = lane < 31 && ((colm >> (lane + 1)) & 1u);
        const bool Wf  = wv  != (int)BGLAB;
        const bool NWf = nwv != (int)BGLAB;
        const bool SWf = swv != (int)BGLAB;

        const int lp = recon(base, r & ~31, c, v);
        if (Wf) {
            if (!(Nf && NWf)) uniteG(lp, recon(base, r & ~31, c - 32, wv));
        } else {
            if (NWf && !Nf) uniteG(lp, recon(base, (r - 1) & ~31, c - 32, nwv));
            if (SWf && !Sf) uniteG(lp, recon(base, (r + 1) & ~31, c - 32, swv));
        }
    }
}

// ---------------- kernel 3: direct-index count + compress + winner (256 thr)-
__global__ __launch_bounds__(256) void k_count() {
    __shared__ int hcnt[1024];
    __shared__ unsigned long long blockmax;

    const int tid = threadIdx.x;
    const int row = tid >> 3;
    const int col4 = (tid & 7) << 2;
    const int b = blockIdx.z;
    const int base = b * HW;
    const int g = base + (((blockIdx.y << 5) + row) << 10) + (blockIdx.x << 5) + col4;

    *(int4*)&hcnt[tid << 2] = make_int4(0, 0, 0, 0);
    if (tid == 0) blockmax = 0ULL;
    __syncthreads();

    const ushort4 lv = *(const ushort4*)&d_label16[g];
    if (lv.x != BGLAB) atomicAdd(&hcnt[lv.x], 1);
    if (lv.y != BGLAB) atomicAdd(&hcnt[lv.y], 1);
    if (lv.z != BGLAB) atomicAdd(&hcnt[lv.z], 1);
    if (lv.w != BGLAB) atomicAdd(&hcnt[lv.w], 1);
    __syncthreads();

    const int4 cnts = *(const int4*)&hcnt[tid << 2];
    const int cv[4] = {cnts.x, cnts.y, cnts.z, cnts.w};
    unsigned long long localmax = 0ULL;
    #pragma unroll
    for (int j = 0; j < 4; ++j) {
        const int cnt = cv[j];
        if (cnt > 0) {
            const int node = recon(base, blockIdx.y << 5, blockIdx.x << 5, (tid << 2) + j);
            int r = node, pc = d_labels[node];
            while (pc != r) { r = pc; pc = d_labels[r]; }
            int xx = node;
            while (xx != r) { int nxt = d_labels[xx]; d_labels[xx] = r; xx = nxt; }

            const int total = atomicAdd(&d_counts[r], cnt) + cnt;
            const unsigned long long key =
                ((unsigned long long)(unsigned)total << 32)
                | (unsigned long long)(0xFFFFFFFFu - (unsigned)r);
            if (key > localmax) localmax = key;
        }
    }
    if (localmax) atomicMax(&blockmax, localmax);
    __syncthreads();

    if (tid == 0 && blockmax != 0ULL) {
        unsigned long long cur = *(volatile unsigned long long*)&d_winner[b];
        if (blockmax > cur) atomicMax(&d_winner[b], blockmax);
    }
}

// ---------------- kernel 4: masked output -----------------------------------
__global__ void k_write(const float* __restrict__ x, float* __restrict__ out) {
    const int i = blockIdx.x * blockDim.x + threadIdx.x;   // over NPIX/4
    const int p4 = i << 2;
    const int b = p4 >> 20;                                // HW = 2^20
    const int p = p4 & (HW - 1);

    const unsigned long long wk = d_winner[b];
    const int wroot = (int)(0xFFFFFFFFu - (unsigned)(wk & 0xFFFFFFFFu)); // no fg -> -1

    const ushort4 lv = ((const ushort4*)d_label16)[i];
    const int base = b * HW;
    const int rowbase = (p >> 10) & ~31;
    const int colbase = p & 0x3E0;

    const bool m0 = (lv.x != BGLAB) && (d_labels[recon(base, rowbase, colbase, lv.x)] == wroot);
    const bool m1 = (lv.y != BGLAB) && (d_labels[recon(base, rowbase, colbase, lv.y)] == wroot);
    const bool m2 = (lv.z != BGLAB) && (d_labels[recon(base, rowbase, colbase, lv.z)] == wroot);
    const bool m3 = (lv.w != BGLAB) && (d_labels[recon(base, rowbase, colbase, lv.w)] == wroot);

    const float* xb = x + (size_t)b * 2 * HW;
    const float4 v0 = *(const float4*)(xb + p);
    const float4 v1 = *(const float4*)(xb + HW + p);

    float4 o0, o1;
    o0.x = m0 ? v0.x : 0.0f;
    o0.y = m1 ? v0.y : 0.0f;
    o0.z = m2 ? v0.z : 0.0f;
    o0.w = m3 ? v0.w : 0.0f;
    o1.x = m0 ? v1.x : 0.0f;
    o1.y = m1 ? v1.y : 0.0f;
    o1.z = m2 ? v1.z : 0.0f;
    o1.w = m3 ? v1.w : 0.0f;

    float* ob = out + (size_t)b * 2 * HW;
    *(float4*)(ob + p) = o0;
    *(float4*)(ob + HW + p) = o1;
}

// ---------------- launcher --------------------------------------------------
extern "C" void kernel_launch(void* const* d_in, const int* in_sizes, int n_in,
                              void* d_out, int out_size) {
    const float* x = (const float*)d_in[0];
    float* out = (float*)d_out;

    dim3 grd(W / 32, H / 32, BATCH);

    k_init_local<<<grd, 256>>>(x);

    const int nb = BATCH * 2 * 31 * 1024;
    k_border<<<(nb + 255) / 256, 256>>>();

    k_count<<<grd, 256>>>();

    k_write<<<(NPIX / 4) / 256, 256>>>(x, out);
}